// round 4
// baseline (speedup 1.0000x reference)
#include <cuda_runtime.h>
#include <math_constants.h>

// Problem constants (fixed by reference)
constexpr int B = 8;
constexpr int N = 4096;
constexpr int M = 4096;

constexpr int THREADS = 128;          // threads per minpass block
constexpr int R       = 4;            // query points per thread (register tile)
constexpr int TN      = THREADS * R;  // 512 query points per block
constexpr int NTILES  = N / TN;       // 8
constexpr int SPLIT   = 16;           // M split into chunks (balance)
constexpr int CHUNK   = M / SPLIT;    // 256 target points per block

constexpr int RBLOCKS = 128;          // reduce blocks (128*256 == B*N)

// Scratch (no allocations allowed)
__device__ float g_rowpart[B * SPLIT * N];
__device__ float g_colpart[B * SPLIT * M];
__device__ float g_acc[4];            // sum_rowmin, sum_sqrt_rowmin, sum_colmin, sum_unc
__device__ unsigned int g_ticket = 0; // last-block finalize ticket (self-resetting)

// ---------------- packed f32x2 helpers (FFMA2 if the arch emits it) ----------
__device__ __forceinline__ unsigned long long pack2(float x, float y) {
    unsigned long long r;
    asm("mov.b64 %0, {%1, %2};" : "=l"(r) : "f"(x), "f"(y));
    return r;
}
__device__ __forceinline__ unsigned long long fma2(unsigned long long a,
                                                   unsigned long long b,
                                                   unsigned long long c) {
    unsigned long long d;
    asm("fma.rn.f32x2 %0, %1, %2, %3;" : "=l"(d) : "l"(a), "l"(b), "l"(c));
    return d;
}
__device__ __forceinline__ void unpack2(unsigned long long v, float& lo, float& hi) {
    asm("mov.b64 {%0, %1}, %2;" : "=f"(lo), "=f"(hi) : "l"(v));
}

// ---------------------------------------------------------------------------
// Fused bidirectional minpass.
//   pass 0: P = pred, T = targ  -> g_rowpart   (min over targets per pred pt)
//   pass 1: P = targ, T = pred  -> g_colpart   (min over preds per target pt)
// Tracks (||t||^2 - 2 p.t); adds ||p||^2 at the end (commutes with min).
// Block (0,0,0) also zeroes g_acc for the downstream reduce (stream-ordered).
// ---------------------------------------------------------------------------
__global__ void __launch_bounds__(THREADS)
minpass_fused(const float* __restrict__ pred, const float* __restrict__ targ)
{
    __shared__ float4 s[CHUNK];   // [2k]   = (-2tx[2k], -2tx[2k+1], -2ty[2k], -2ty[2k+1])
                                  // [2k+1] = (-2tz[2k], -2tz[2k+1],  t2[2k],   t2[2k+1])
    const int tid   = threadIdx.x;
    const int split = blockIdx.x;
    const int ntile = blockIdx.y;
    const int zz    = blockIdx.z;        // [0, 2*B)
    const int b     = zz & (B - 1);
    const int pass  = zz >> 3;
    const int n0    = ntile * TN;
    const int mc0   = split * CHUNK;

    if ((split | ntile | zz) == 0 && tid < 4) g_acc[tid] = 0.f;  // pre-reduce zero

    const float* P = pass ? targ : pred;
    const float* T = pass ? pred : targ;
    float* outp    = pass ? g_colpart : g_rowpart;

    // Load + transform target chunk into smem (CHUNK/2 == THREADS pairs)
    {
        const int ma = 2 * tid;
        const float* ta = T + ((size_t)b * M + mc0 + ma) * 3;
        const float ax = ta[0], ay = ta[1], az = ta[2];
        const float bx = ta[3], by = ta[4], bz = ta[5];
        const float a2 = ax * ax + ay * ay + az * az;
        const float b2 = bx * bx + by * by + bz * bz;
        s[ma]     = make_float4(-2.f * ax, -2.f * bx, -2.f * ay, -2.f * by);
        s[ma + 1] = make_float4(-2.f * az, -2.f * bz, a2, b2);
    }

    // Load R query points into registers, broadcast-packed
    unsigned long long px2[R], py2[R], pz2[R];
    float pn2[R], rlo[R], rhi[R];
#pragma unroll
    for (int j = 0; j < R; j++) {
        const int nn = n0 + tid + THREADS * j;
        const float* p = P + ((size_t)b * N + nn) * 3;
        const float x = p[0], y = p[1], z = p[2];
        pn2[j] = x * x + y * y + z * z;
        px2[j] = pack2(x, x);
        py2[j] = pack2(y, y);
        pz2[j] = pack2(z, z);
        rlo[j] = CUDART_INF_F;
        rhi[j] = CUDART_INF_F;
    }
    __syncthreads();

    const ulonglong2* s64 = reinterpret_cast<const ulonglong2*>(s);
#pragma unroll 4
    for (int k = 0; k < CHUNK / 2; k++) {
        const ulonglong2 v0 = s64[2 * k];       // {tx2 pair, ty2 pair}
        const ulonglong2 v1 = s64[2 * k + 1];   // {tz2 pair, t2 pair}
#pragma unroll
        for (int j = 0; j < R; j++) {
            unsigned long long acc = fma2(pz2[j], v1.x, v1.y);  // -2 z tz + t2
            acc = fma2(py2[j], v0.y, acc);
            acc = fma2(px2[j], v0.x, acc);                      // t2 - 2 p.t (x2)
            float lo, hi;
            unpack2(acc, lo, hi);
            rlo[j] = fminf(rlo[j], lo);
            rhi[j] = fminf(rhi[j], hi);
        }
    }

    float* o = outp + (size_t)(b * SPLIT + split) * N;
#pragma unroll
    for (int j = 0; j < R; j++) {
        const int nn = n0 + tid + THREADS * j;
        o[nn] = pn2[j] + fminf(rlo[j], rhi[j]);   // partial min of true squared dist
    }
}

// ---------------------------------------------------------------------------
// Reduce + fused finalize (last-block ticket). One idx per thread; 33
// independent L2-resident loads -> latency hidden by 32K threads + MLP.
// ---------------------------------------------------------------------------
__global__ void __launch_bounds__(256) reduce_final_kernel(const float* __restrict__ unc,
                                                           float* __restrict__ out)
{
    const int idx = blockIdx.x * blockDim.x + threadIdx.x;   // [0, B*N)
    const int b = idx >> 12;          // N == 4096
    const int n = idx & (N - 1);

    const float* p = g_rowpart + (size_t)b * SPLIT * N + n;
    float m = p[0];
#pragma unroll
    for (int s2 = 1; s2 < SPLIT; s2++) m = fminf(m, __ldg(p + (size_t)s2 * N));
    float s_row  = m;
    float s_sqrt = sqrtf(fmaxf(m, 0.f));

    const float* q = g_colpart + (size_t)b * SPLIT * M + n;
    float mc = q[0];
#pragma unroll
    for (int s2 = 1; s2 < SPLIT; s2++) mc = fminf(mc, __ldg(q + (size_t)s2 * M));
    float s_col = mc;

    float s_unc = unc[idx];

    // warp reduce, then one atomicAdd per warp
#pragma unroll
    for (int o = 16; o > 0; o >>= 1) {
        s_row  += __shfl_down_sync(0xffffffffu, s_row,  o);
        s_sqrt += __shfl_down_sync(0xffffffffu, s_sqrt, o);
        s_col  += __shfl_down_sync(0xffffffffu, s_col,  o);
        s_unc  += __shfl_down_sync(0xffffffffu, s_unc,  o);
    }
    if ((threadIdx.x & 31) == 0) {
        atomicAdd(&g_acc[0], s_row);
        atomicAdd(&g_acc[1], s_sqrt);
        atomicAdd(&g_acc[2], s_col);
        atomicAdd(&g_acc[3], s_unc);
    }

    // last-block finalize
    __syncthreads();                       // all warps' atomics issued
    __threadfence();                       // make them globally visible
    __shared__ bool s_last;
    if (threadIdx.x == 0)
        s_last = (atomicAdd(&g_ticket, 1u) == (unsigned)(RBLOCKS - 1));
    __syncthreads();
    if (s_last && threadIdx.x == 0) {
        const float inv = 1.0f / (float)(B * N);       // B*N == B*M
        const float chamfer = (g_acc[0] + g_acc[2]) * inv;
        const float emd     = g_acc[1] * inv;
        const float u       = g_acc[3] * inv;
        out[0] = chamfer * 1.0f + emd * 0.5f + u * 0.01f;
        g_ticket = 0;                      // reset for next graph replay
    }
}

// ---------------------------------------------------------------------------
extern "C" void kernel_launch(void* const* d_in, const int* in_sizes, int n_in,
                              void* d_out, int out_size)
{
    const float* pred = (const float*)d_in[0];   // [B, N, 3]
    const float* targ = (const float*)d_in[1];   // [B, M, 3]
    const float* unc  = (const float*)d_in[2];   // [B, N]
    float* out = (float*)d_out;

    dim3 grid(SPLIT, NTILES, 2 * B);             // 16 x 8 x 16 = 2048 blocks
    minpass_fused<<<grid, THREADS>>>(pred, targ);

    reduce_final_kernel<<<RBLOCKS, 256>>>(unc, out);   // 128 blocks x 256
}

// round 6
// speedup vs baseline: 1.0421x; 1.0421x over previous
#include <cuda_runtime.h>
#include <math_constants.h>

// Problem constants (fixed by reference)
constexpr int B = 8;
constexpr int N = 4096;
constexpr int M = 4096;

constexpr int THREADS = 128;          // threads per block
constexpr int R       = 4;            // query points per thread
constexpr int TN      = THREADS * R;  // 512 query points per block
constexpr int NTILES  = N / TN;       // 8
constexpr int SPLIT   = 16;           // M split into chunks
constexpr int CHUNK   = M / SPLIT;    // 256 target points per block

constexpr int TOTAL_BLOCKS = SPLIT * NTILES * 2 * B;    // 2048
constexpr int REDUCERS     = 128;                       // last 128 blocks reduce
constexpr int PTS_PER_RED  = (B * N) / REDUCERS;        // 256 points each

// Scratch (no allocations allowed)
__device__ float g_rowpart[B * SPLIT * N];
__device__ float g_colpart[B * SPLIT * M];
__device__ float g_acc[4];            // sum_rowmin, sum_sqrt_rowmin, sum_colmin, sum_unc
__device__ unsigned int g_count  = 0; // minpass completion ticket
__device__ unsigned int g_count2 = 0; // reducer completion ticket

// ---------------------------------------------------------------------------
// One fused kernel:
//   Phase 1 (all 2048 blocks): bidirectional min pass over a (512 query x 256
//     target) tile. pass = blockIdx.z>>3. Tracks (||t||^2 - 2 p.t); adds
//     ||p||^2 at the end (commutes with min). Writes per-chunk partial mins.
//   Phase 2 (last 128 blocks to finish): after a global ticket barrier, each
//     reduces 256 points (min over 16 chunks both directions, sum, sqrt-sum,
//     uncertainty sum) into g_acc; the last reducer finalizes the scalar loss
//     and resets the tickets (deterministic across graph replays).
// ---------------------------------------------------------------------------
__global__ void __launch_bounds__(THREADS)
fused_loss_kernel(const float* __restrict__ pred, const float* __restrict__ targ,
                  const float* __restrict__ unc,  float* __restrict__ out)
{
    __shared__ float4 s[CHUNK];          // (-2tx, -2ty, -2tz, ||t||^2)
    __shared__ unsigned int s_ticket;

    const int tid   = threadIdx.x;
    const int split = blockIdx.x;
    const int ntile = blockIdx.y;
    const int zz    = blockIdx.z;        // [0, 2*B)
    const int b     = zz & (B - 1);
    const int pass  = zz >> 3;
    const int n0    = ntile * TN;
    const int mc0   = split * CHUNK;

    if ((split | ntile | zz) == 0 && tid < 4) g_acc[tid] = 0.f;  // pre-reduce zero

    const float* P = pass ? targ : pred;
    const float* T = pass ? pred : targ;
    float* outp    = pass ? g_colpart : g_rowpart;

    // Load + transform target chunk into smem (2 targets per thread)
#pragma unroll
    for (int i = tid; i < CHUNK; i += THREADS) {
        const float* ta = T + ((size_t)b * M + mc0 + i) * 3;
        const float x = ta[0], y = ta[1], z = ta[2];
        s[i] = make_float4(-2.f * x, -2.f * y, -2.f * z, x * x + y * y + z * z);
    }

    // Load R query points into registers
    float px[R], py[R], pz[R], pn2[R], r[R];
#pragma unroll
    for (int j = 0; j < R; j++) {
        const int nn = n0 + tid + THREADS * j;
        const float* p = P + ((size_t)b * N + nn) * 3;
        px[j] = p[0]; py[j] = p[1]; pz[j] = p[2];
        pn2[j] = px[j] * px[j] + py[j] * py[j] + pz[j] * pz[j];
        r[j] = CUDART_INF_F;
    }
    __syncthreads();

    // Scalar inner loop: 3 FFMA + 1 FMNMX per eval, LDS.128 amortized over R.
#pragma unroll 4
    for (int k = 0; k < CHUNK; k++) {
        const float4 v = s[k];
#pragma unroll
        for (int j = 0; j < R; j++) {
            float d = fmaf(pz[j], v.z, v.w);
            d = fmaf(py[j], v.y, d);
            d = fmaf(px[j], v.x, d);          // ||t||^2 - 2 p.t
            r[j] = fminf(r[j], d);
        }
    }

    float* o = outp + (size_t)(b * SPLIT + split) * N;
#pragma unroll
    for (int j = 0; j < R; j++) {
        const int nn = n0 + tid + THREADS * j;
        o[nn] = pn2[j] + r[j];               // partial min of true squared dist
    }

    // ---- global ticket: last REDUCERS finishers become reducer blocks ----
    __threadfence();                         // partial writes visible
    __syncthreads();                         // all warps' writes issued
    if (tid == 0) s_ticket = atomicAdd(&g_count, 1u);
    __syncthreads();
    const unsigned int my = s_ticket;
    if (my < (unsigned)(TOTAL_BLOCKS - REDUCERS)) return;

    // Wait for every block's partials
    if (tid == 0) {
        while (*((volatile unsigned int*)&g_count) < (unsigned)TOTAL_BLOCKS)
            __nanosleep(64);
    }
    __syncthreads();
    __threadfence();                         // acquire partials

    // ---- Phase 2: reduce 256 points ----
    const int rid  = (int)my - (TOTAL_BLOCKS - REDUCERS);   // [0, 128)
    const int base = rid * PTS_PER_RED;

    float s_row = 0.f, s_sqrt = 0.f, s_col = 0.f, s_unc = 0.f;
#pragma unroll
    for (int it = 0; it < PTS_PER_RED / THREADS; it++) {     // 2 iterations
        const int idx = base + it * THREADS + tid;           // [0, B*N)
        const int bb = idx >> 12;            // N == 4096
        const int nn = idx & (N - 1);

        const float* p = g_rowpart + (size_t)bb * SPLIT * N + nn;
        float m = p[0];
#pragma unroll
        for (int s2 = 1; s2 < SPLIT; s2++) m = fminf(m, __ldg(p + (size_t)s2 * N));
        s_row  += m;
        s_sqrt += sqrtf(fmaxf(m, 0.f));

        const float* q = g_colpart + (size_t)bb * SPLIT * M + nn;
        float mc = q[0];
#pragma unroll
        for (int s2 = 1; s2 < SPLIT; s2++) mc = fminf(mc, __ldg(q + (size_t)s2 * M));
        s_col += mc;

        s_unc += unc[idx];
    }

    // warp reduce, then one atomicAdd per warp
#pragma unroll
    for (int o = 16; o > 0; o >>= 1) {
        s_row  += __shfl_down_sync(0xffffffffu, s_row,  o);
        s_sqrt += __shfl_down_sync(0xffffffffu, s_sqrt, o);
        s_col  += __shfl_down_sync(0xffffffffu, s_col,  o);
        s_unc  += __shfl_down_sync(0xffffffffu, s_unc,  o);
    }
    if ((tid & 31) == 0) {
        atomicAdd(&g_acc[0], s_row);
        atomicAdd(&g_acc[1], s_sqrt);
        atomicAdd(&g_acc[2], s_col);
        atomicAdd(&g_acc[3], s_unc);
    }

    // ---- finalize: last reducer computes the scalar loss, resets tickets ----
    __threadfence();
    __syncthreads();
    if (tid == 0) {
        const unsigned int done = atomicAdd(&g_count2, 1u);
        if (done == (unsigned)(REDUCERS - 1)) {
            const float inv = 1.0f / (float)(B * N);         // B*N == B*M
            const float chamfer = (g_acc[0] + g_acc[2]) * inv;
            const float emd     = g_acc[1] * inv;
            const float u       = g_acc[3] * inv;
            out[0] = chamfer * 1.0f + emd * 0.5f + u * 0.01f;
            g_count  = 0;                    // reset for next graph replay
            g_count2 = 0;
        }
    }
}

// ---------------------------------------------------------------------------
extern "C" void kernel_launch(void* const* d_in, const int* in_sizes, int n_in,
                              void* d_out, int out_size)
{
    const float* pred = (const float*)d_in[0];   // [B, N, 3]
    const float* targ = (const float*)d_in[1];   // [B, M, 3]
    const float* unc  = (const float*)d_in[2];   // [B, N]
    float* out = (float*)d_out;

    dim3 grid(SPLIT, NTILES, 2 * B);             // 16 x 8 x 16 = 2048 blocks
    fused_loss_kernel<<<grid, THREADS>>>(pred, targ, unc, out);
}